// round 5
// baseline (speedup 1.0000x reference)
#include <cuda_runtime.h>
#include <math.h>
#include <stdint.h>

#define N_NODES 100000
#define N_EDGES 1600000
#define NFEAT 512
#define HID 128
#define NCLS 40

#define SCAN_B 1024
#define NBLK ((N_NODES + SCAN_B - 1) / SCAN_B)   // 98

// ---------------- device scratch (no allocations allowed) ----------------
__device__ int   g_cnt[N_NODES];
__device__ int   g_start[N_NODES];
__device__ int   g_cursor[N_NODES];
__device__ float g_inv_sqrt[N_NODES];
__device__ float g_invdeg[N_NODES];
__device__ int   g_blocksum[NBLK];
__device__ int   g_blockoff[NBLK];
__device__ int2  g_edge[N_EDGES];                // .x = src, .y = coef bits
__device__ float g_h1[(size_t)N_NODES * HID];    // x @ W1
__device__ float g_a1[(size_t)N_NODES * HID];    // relu(conv1)
__device__ float g_h2[(size_t)N_NODES * NCLS];   // a1 @ W2

// ---------------- CSR build ----------------
__global__ void zero_cnt_kernel() {
    int i = blockIdx.x * blockDim.x + threadIdx.x;
    if (i < N_NODES) g_cnt[i] = 0;
}

__global__ void count_kernel(const int* __restrict__ dst) {
    int e = blockIdx.x * blockDim.x + threadIdx.x;
    if (e < N_EDGES) atomicAdd(&g_cnt[dst[e]], 1);
}

__global__ void scan_blocks_kernel() {
    __shared__ int s[SCAN_B];
    int tid = threadIdx.x;
    int i = blockIdx.x * SCAN_B + tid;
    int v = (i < N_NODES) ? g_cnt[i] : 0;
    s[tid] = v;
    __syncthreads();
    #pragma unroll
    for (int off = 1; off < SCAN_B; off <<= 1) {
        int t = (tid >= off) ? s[tid - off] : 0;
        __syncthreads();
        s[tid] += t;
        __syncthreads();
    }
    if (i < N_NODES) g_start[i] = s[tid] - v;       // exclusive within block
    if (tid == SCAN_B - 1) g_blocksum[blockIdx.x] = s[tid];
}

__global__ void scan_sums_kernel() {
    __shared__ int s[128];
    int tid = threadIdx.x;
    int v = (tid < NBLK) ? g_blocksum[tid] : 0;
    s[tid] = v;
    __syncthreads();
    #pragma unroll
    for (int off = 1; off < 128; off <<= 1) {
        int t = (tid >= off) ? s[tid - off] : 0;
        __syncthreads();
        s[tid] += t;
        __syncthreads();
    }
    if (tid < NBLK) g_blockoff[tid] = s[tid] - v;   // exclusive
}

__global__ void finalize_nodes_kernel() {
    int i = blockIdx.x * blockDim.x + threadIdx.x;
    if (i >= N_NODES) return;
    g_start[i] += g_blockoff[i >> 10];
    g_cursor[i] = 0;
    float deg = (float)g_cnt[i] + 1.0f;
    g_inv_sqrt[i] = rsqrtf(deg);
    g_invdeg[i]   = 1.0f / deg;
}

__global__ void scatter_kernel(const int* __restrict__ src_a,
                               const int* __restrict__ dst_a) {
    int e = blockIdx.x * blockDim.x + threadIdx.x;
    if (e >= N_EDGES) return;
    int s = src_a[e];
    int d = dst_a[e];
    int pos = g_start[d] + atomicAdd(&g_cursor[d], 1);
    float cf = g_inv_sqrt[s] * g_inv_sqrt[d];
    g_edge[pos] = make_int2(s, __float_as_int(cf));
}

// ---------------- GEMM1: h1 = x @ W1 via tf32 mma.sync, double-buffered -----
// Block tile 128x128, K tile 32, 256 threads = 8 warps (4 M x 2 N).
// Each warp: 32x64 via 2x8 grid of m16n8k8 mma tiles.

__device__ __forceinline__ uint32_t f2tf32(float f) {
    uint32_t u;
    asm("cvt.rna.tf32.f32 %0, %1;" : "=r"(u) : "f"(f));
    return u;
}

__device__ __forceinline__ void mma_tf32(float* c, const uint32_t* a,
                                         uint32_t b0, uint32_t b1) {
    asm volatile(
        "mma.sync.aligned.m16n8k8.row.col.f32.tf32.tf32.f32 "
        "{%0,%1,%2,%3}, {%4,%5,%6,%7}, {%8,%9}, {%0,%1,%2,%3};"
        : "+f"(c[0]), "+f"(c[1]), "+f"(c[2]), "+f"(c[3])
        : "r"(a[0]), "r"(a[1]), "r"(a[2]), "r"(a[3]), "r"(b0), "r"(b1));
}

#define G1_AS 36    // A smem row stride (pad): (4m+k)%32 bijective -> conflict-free
#define G1_BS 136   // B smem row stride (pad): (8k+n)%32 bijective -> conflict-free
#define A_STAGE (128 * G1_AS)
#define B_STAGE (32 * G1_BS)
#define NKT (NFEAT / 32)   // 16 k-tiles

__global__ __launch_bounds__(256) void gemm1_mma_kernel(const float* __restrict__ A,
                                                        const float* __restrict__ B) {
    __shared__ uint32_t As[2 * A_STAGE];  // [m][k] tf32 bits, 2 stages
    __shared__ uint32_t Bs[2 * B_STAGE];  // [k][n] tf32 bits, 2 stages
    const int tid  = threadIdx.x;
    const int lane = tid & 31;
    const int wid  = tid >> 5;
    const int wm   = wid & 3;       // warp M index (0..3) -> 32 rows
    const int wn   = wid >> 2;      // warp N index (0..1) -> 64 cols
    const int g    = lane >> 2;     // groupID
    const int tg   = lane & 3;      // thread-in-group
    const int bm0  = blockIdx.x * 128;

    float acc[2][8][4];
    #pragma unroll
    for (int i = 0; i < 2; i++)
        #pragma unroll
        for (int j = 0; j < 8; j++)
            #pragma unroll
            for (int r = 0; r < 4; r++) acc[i][j][r] = 0.f;

    float4 aR[4], bR[4];

    // register-staged tile load (GMEM -> regs)
    auto load_tiles = [&](int k0) {
        #pragma unroll
        for (int r = 0; r < 4; r++) {
            int idx = tid + r * 256;        // 0..1023
            int row = idx >> 3;             // 8 float4 per A row
            int col = (idx & 7) * 4;
            int gr  = bm0 + row;
            aR[r] = (gr < N_NODES)
                ? *(const float4*)&A[(size_t)gr * NFEAT + k0 + col]
                : make_float4(0.f, 0.f, 0.f, 0.f);
        }
        #pragma unroll
        for (int r = 0; r < 4; r++) {
            int idx = tid + r * 256;
            int row = idx >> 5;             // 32 float4 per B row
            int col = (idx & 31) * 4;
            bR[r] = *(const float4*)&B[(size_t)(k0 + row) * HID + col];
        }
    };

    // regs -> smem stage (with tf32 rounding)
    auto store_tiles = [&](int st) {
        uint32_t* Ab = As + st * A_STAGE;
        uint32_t* Bb = Bs + st * B_STAGE;
        #pragma unroll
        for (int r = 0; r < 4; r++) {
            int idx = tid + r * 256;
            int row = idx >> 3;
            int col = (idx & 7) * 4;
            uint32_t* p = &Ab[row * G1_AS + col];
            p[0] = f2tf32(aR[r].x); p[1] = f2tf32(aR[r].y);
            p[2] = f2tf32(aR[r].z); p[3] = f2tf32(aR[r].w);
        }
        #pragma unroll
        for (int r = 0; r < 4; r++) {
            int idx = tid + r * 256;
            int row = idx >> 5;
            int col = (idx & 31) * 4;
            uint32_t* p = &Bb[row * G1_BS + col];
            p[0] = f2tf32(bR[r].x); p[1] = f2tf32(bR[r].y);
            p[2] = f2tf32(bR[r].z); p[3] = f2tf32(bR[r].w);
        }
    };

    // prologue: tile 0 into stage 0
    load_tiles(0);
    store_tiles(0);
    __syncthreads();

    for (int kt = 0; kt < NKT; kt++) {
        int st = kt & 1;
        if (kt + 1 < NKT) load_tiles((kt + 1) * 32);   // LDG in flight during compute

        const uint32_t* Ab = As + st * A_STAGE;
        const uint32_t* Bb = Bs + st * B_STAGE;
        #pragma unroll
        for (int kc = 0; kc < 32; kc += 8) {
            uint32_t af[2][4];
            #pragma unroll
            for (int i = 0; i < 2; i++) {
                int m = wm * 32 + i * 16;
                af[i][0] = Ab[(m + g)     * G1_AS + kc + tg];
                af[i][1] = Ab[(m + 8 + g) * G1_AS + kc + tg];
                af[i][2] = Ab[(m + g)     * G1_AS + kc + tg + 4];
                af[i][3] = Ab[(m + 8 + g) * G1_AS + kc + tg + 4];
            }
            #pragma unroll
            for (int j = 0; j < 8; j++) {
                int n = wn * 64 + j * 8;
                uint32_t b0 = Bb[(kc + tg)     * G1_BS + n + g];
                uint32_t b1 = Bb[(kc + tg + 4) * G1_BS + n + g];
                mma_tf32(acc[0][j], af[0], b0, b1);
                mma_tf32(acc[1][j], af[1], b0, b1);
            }
        }

        if (kt + 1 < NKT) store_tiles((kt + 1) & 1);   // write other stage
        __syncthreads();
    }

    // epilogue: c0/c1 -> (row=g, col=2*tg), c2/c3 -> (row=g+8)
    #pragma unroll
    for (int i = 0; i < 2; i++) {
        #pragma unroll
        for (int j = 0; j < 8; j++) {
            int col = wn * 64 + j * 8 + tg * 2;
            int r0  = bm0 + wm * 32 + i * 16 + g;
            int r1  = r0 + 8;
            if (r0 < N_NODES)
                *(float2*)&g_h1[(size_t)r0 * HID + col] =
                    make_float2(acc[i][j][0], acc[i][j][1]);
            if (r1 < N_NODES)
                *(float2*)&g_h1[(size_t)r1 * HID + col] =
                    make_float2(acc[i][j][2], acc[i][j][3]);
        }
    }
}

// ---------------- agg1: a1 = relu(sum_e coef*h1[src] + h1*invdeg + b1) ------
// One warp per node; edge loop unrolled x4 for MLP.
__global__ void agg1_kernel(const float* __restrict__ b1) {
    int gw = (blockIdx.x * blockDim.x + threadIdx.x) >> 5;
    int lane = threadIdx.x & 31;
    if (gw >= N_NODES) return;
    int node = gw;
    const float4* H = (const float4*)g_h1;
    float4 self = H[node * 32 + lane];
    float sd = g_invdeg[node];
    float4 acc;
    acc.x = self.x * sd; acc.y = self.y * sd;
    acc.z = self.z * sd; acc.w = self.w * sd;
    int s = g_start[node];
    int c = g_cnt[node];
    int e = 0;
    for (; e + 4 <= c; e += 4) {
        int2 ed0 = g_edge[s + e];
        int2 ed1 = g_edge[s + e + 1];
        int2 ed2 = g_edge[s + e + 2];
        int2 ed3 = g_edge[s + e + 3];
        float4 v0 = H[ed0.x * 32 + lane];
        float4 v1 = H[ed1.x * 32 + lane];
        float4 v2 = H[ed2.x * 32 + lane];
        float4 v3 = H[ed3.x * 32 + lane];
        float c0 = __int_as_float(ed0.y), c1 = __int_as_float(ed1.y);
        float c2 = __int_as_float(ed2.y), c3 = __int_as_float(ed3.y);
        acc.x += v0.x * c0 + v1.x * c1 + v2.x * c2 + v3.x * c3;
        acc.y += v0.y * c0 + v1.y * c1 + v2.y * c2 + v3.y * c3;
        acc.z += v0.z * c0 + v1.z * c1 + v2.z * c2 + v3.z * c3;
        acc.w += v0.w * c0 + v1.w * c1 + v2.w * c2 + v3.w * c3;
    }
    for (; e < c; e++) {
        int2 ed = g_edge[s + e];
        float cf = __int_as_float(ed.y);
        float4 v = H[ed.x * 32 + lane];
        acc.x += v.x * cf; acc.y += v.y * cf;
        acc.z += v.z * cf; acc.w += v.w * cf;
    }
    float4 bb = ((const float4*)b1)[lane];
    acc.x = fmaxf(acc.x + bb.x, 0.f);
    acc.y = fmaxf(acc.y + bb.y, 0.f);
    acc.z = fmaxf(acc.z + bb.z, 0.f);
    acc.w = fmaxf(acc.w + bb.w, 0.f);
    ((float4*)g_a1)[node * 32 + lane] = acc;
}

// ---------------- GEMM2: h2 = a1 @ W2 (100000x128 @ 128x40), fp32 ----------
__global__ __launch_bounds__(128) void gemm2_kernel(const float* __restrict__ W2) {
    __shared__ float Ws[HID * NCLS];
    __shared__ float As2[32][132];
    int tid = threadIdx.x;
    for (int i = tid; i < HID * NCLS; i += 128) Ws[i] = W2[i];
    int base = blockIdx.x * 32;
    for (int i = tid; i < 32 * HID; i += 128) {
        int row = i >> 7;
        int col = i & 127;
        int gr = base + row;
        As2[row][col] = (gr < N_NODES) ? g_a1[(size_t)gr * HID + col] : 0.f;
    }
    __syncthreads();
    int nl = tid >> 2;
    int cg = (tid & 3) * 10;
    float acc[10] = {};
    #pragma unroll 8
    for (int k = 0; k < HID; k++) {
        float a = As2[nl][k];
        #pragma unroll
        for (int j = 0; j < 10; j++)
            acc[j] += a * Ws[k * NCLS + cg + j];
    }
    int gr = base + nl;
    if (gr < N_NODES) {
        #pragma unroll
        for (int j = 0; j < 10; j++)
            g_h2[(size_t)gr * NCLS + cg + j] = acc[j];
    }
}

// ---------------- agg2 + bias + log_softmax ----------------
__global__ void agg2_kernel(const float* __restrict__ b2, float* __restrict__ out) {
    int gw = (blockIdx.x * blockDim.x + threadIdx.x) >> 5;
    int lane = threadIdx.x & 31;
    if (gw >= N_NODES) return;
    int node = gw;
    const float* H = g_h2;
    float sd = g_invdeg[node];
    float acc0 = H[(size_t)node * NCLS + lane] * sd;
    float acc1 = (lane < 8) ? H[(size_t)node * NCLS + 32 + lane] * sd : 0.f;
    int s = g_start[node];
    int c = g_cnt[node];
    int e = 0;
    for (; e + 4 <= c; e += 4) {
        int2 ed0 = g_edge[s + e];
        int2 ed1 = g_edge[s + e + 1];
        int2 ed2 = g_edge[s + e + 2];
        int2 ed3 = g_edge[s + e + 3];
        float v00 = H[(size_t)ed0.x * NCLS + lane];
        float v10 = H[(size_t)ed1.x * NCLS + lane];
        float v20 = H[(size_t)ed2.x * NCLS + lane];
        float v30 = H[(size_t)ed3.x * NCLS + lane];
        float c0 = __int_as_float(ed0.y), c1 = __int_as_float(ed1.y);
        float c2 = __int_as_float(ed2.y), c3 = __int_as_float(ed3.y);
        acc0 += v00 * c0 + v10 * c1 + v20 * c2 + v30 * c3;
        if (lane < 8) {
            float v01 = H[(size_t)ed0.x * NCLS + 32 + lane];
            float v11 = H[(size_t)ed1.x * NCLS + 32 + lane];
            float v21 = H[(size_t)ed2.x * NCLS + 32 + lane];
            float v31 = H[(size_t)ed3.x * NCLS + 32 + lane];
            acc1 += v01 * c0 + v11 * c1 + v21 * c2 + v31 * c3;
        }
    }
    for (; e < c; e++) {
        int2 ed = g_edge[s + e];
        float cf = __int_as_float(ed.y);
        acc0 += H[(size_t)ed.x * NCLS + lane] * cf;
        if (lane < 8) acc1 += H[(size_t)ed.x * NCLS + 32 + lane] * cf;
    }
    acc0 += b2[lane];
    if (lane < 8) acc1 += b2[32 + lane];
    float m = acc0;
    if (lane < 8) m = fmaxf(m, acc1);
    #pragma unroll
    for (int off = 16; off > 0; off >>= 1)
        m = fmaxf(m, __shfl_xor_sync(0xffffffffu, m, off));
    float sum = expf(acc0 - m) + ((lane < 8) ? expf(acc1 - m) : 0.f);
    #pragma unroll
    for (int off = 16; off > 0; off >>= 1)
        sum += __shfl_xor_sync(0xffffffffu, sum, off);
    float lse = m + logf(sum);
    out[(size_t)node * NCLS + lane] = acc0 - lse;
    if (lane < 8) out[(size_t)node * NCLS + 32 + lane] = acc1 - lse;
}

// ---------------- launch ----------------
extern "C" void kernel_launch(void* const* d_in, const int* in_sizes, int n_in,
                              void* d_out, int out_size) {
    const float* x   = (const float*)d_in[0];
    const int*   ei  = (const int*)d_in[1];
    const float* W1  = (const float*)d_in[2];
    const float* b1  = (const float*)d_in[3];
    const float* W2  = (const float*)d_in[4];
    const float* b2  = (const float*)d_in[5];
    float* out = (float*)d_out;
    const int* src = ei;
    const int* dst = ei + N_EDGES;

    int nb_n = (N_NODES + 255) / 256;
    int nb_e = (N_EDGES + 255) / 256;

    zero_cnt_kernel<<<nb_n, 256>>>();
    count_kernel<<<nb_e, 256>>>(dst);
    scan_blocks_kernel<<<NBLK, SCAN_B>>>();
    scan_sums_kernel<<<1, 128>>>();
    finalize_nodes_kernel<<<nb_n, 256>>>();
    scatter_kernel<<<nb_e, 256>>>(src, dst);

    gemm1_mma_kernel<<<(N_NODES + 127) / 128, 256>>>(x, W1);

    agg1_kernel<<<(N_NODES + 7) / 8, 256>>>(b1);

    gemm2_kernel<<<(N_NODES + 31) / 32, 128>>>(W2);

    agg2_kernel<<<(N_NODES + 7) / 8, 256>>>(b2, out);
}